// round 2
// baseline (speedup 1.0000x reference)
#include <cuda_runtime.h>
#include <cstdint>
#include <math.h>

// Problem constants
#define P     48
#define FLEN  168
#define HALF  84     // t-split: each CTA handles one half of the forecast horizon
#define HIST  336
#define HOFF  288    // HIST - P

// Precomputed affine map: out[b,t] = g_C[t] + sum_k g_G[k*FLEN+t] * enc_l[b*HIST+HOFF+k]
__device__ float g_G[P * FLEN];
__device__ float g_C[FLEN];
__device__ float g_lv;

typedef unsigned long long ull;

__device__ __forceinline__ ull pack2(float a, float b) {
    ull r; asm("mov.b64 %0, {%1, %2};" : "=l"(r) : "f"(a), "f"(b)); return r;
}
__device__ __forceinline__ void unpack2(ull v, float& a, float& b) {
    asm("mov.b64 {%0, %1}, %2;" : "=f"(a), "=f"(b) : "l"(v));
}
// Packed fp32x2 FMA (Blackwell 2x fp32 path; only emitted from PTX fma.rn.f32x2)
__device__ __forceinline__ ull ffma2(ull a, ull b, ull c) {
    ull d; asm("fma.rn.f32x2 %0, %1, %2, %3;" : "=l"(d) : "l"(a), "l"(b), "l"(c)); return d;
}

// ---------------------------------------------------------------------------
// Kernel 1: tiny precompute of the affine map (G, C, logvar const).
// The AR scan is affine in the initial window: track the impulse response
// h[k][i] = d(history[i]) / d(s0[k]) for k<P, and h[P] = the constant term.
// ---------------------------------------------------------------------------
__global__ void precompute_kernel(const float* __restrict__ phi,
                                  const float* __restrict__ bias,
                                  const float* __restrict__ log_sigma2,
                                  const float* __restrict__ mu_p,
                                  const float* __restrict__ sigma_p) {
    __shared__ float h[P + 1][221];   // 221 odd pitch -> conflict-free
    const int k = threadIdx.x;

    float ph[P];
#pragma unroll
    for (int j = 0; j < P; j++) ph[j] = phi[j];

    if (k <= P) {
#pragma unroll
        for (int i = 0; i < P; i++) h[k][i] = (k == i) ? 1.0f : 0.0f;  // k==P row: zeros
        const float b0 = (k == P) ? bias[0] : 0.0f;
        for (int t = 0; t < FLEN; t++) {
            float s0 = 0.f, s1 = 0.f, s2 = 0.f, s3 = 0.f;
#pragma unroll
            for (int j = 0; j < P; j += 4) {
                s0 += ph[j + 0] * h[k][t + j + 0];
                s1 += ph[j + 1] * h[k][t + j + 1];
                s2 += ph[j + 2] * h[k][t + j + 2];
                s3 += ph[j + 3] * h[k][t + j + 3];
            }
            h[k][P + t] = b0 + ((s0 + s1) + (s2 + s3));
        }
    }
    __syncthreads();

    const float mu = *mu_p;
    const float sg = *sigma_p;

    // Fold standardization + un-standardization into C and scale G by sigma:
    // out = mu + sg*c_t + sum_k sg*W[t,k]*( (y_raw-mu)/sg ) ; absorb into raw-space affine.
    for (int t = threadIdx.x; t < FLEN; t += blockDim.x) {
        float sum = 0.0f;
        for (int kk = 0; kk < P; kk++) sum += h[kk][P + t];
        g_C[t] = mu + sg * h[P][P + t] - mu * sum;
    }
    for (int idx = threadIdx.x; idx < P * FLEN; idx += blockDim.x) {
        const int kk = idx / FLEN;
        const int t  = idx - kk * FLEN;
        g_G[idx] = h[kk][P + t];
    }
    if (threadIdx.x == 0) g_lv = log_sigma2[0] + 2.0f * logf(sg);
}

// ---------------------------------------------------------------------------
// Kernel 2: apply. 1 row per thread; f32x2 lanes = (t, t+1) so G comes out of
// shared already packed (broadcast LDS.128). CTA handles one t-half (84 cols),
// so smem is 16.5KB and occupancy can reach 8 CTAs/SM.
// ---------------------------------------------------------------------------
#define TPB 128

__global__ void __launch_bounds__(TPB, 8)
forecast_kernel(const float* __restrict__ enc_l, float* __restrict__ out, int B) {
    __shared__ float Gs[P * HALF];   // Gs[k*HALF + tt], tt local to this half
    __shared__ float Cs[HALF];

    const int half   = blockIdx.x & 1;
    const int rowblk = blockIdx.x >> 1;
    const int toff   = half * HALF;

    // Stage this half's G slice + C slice into shared (float4, coalesced-ish)
    for (int i = threadIdx.x; i < (P * HALF) / 4; i += TPB) {
        const int kk = i / (HALF / 4);
        const int t4 = i - kk * (HALF / 4);
        ((float4*)Gs)[i] = *(const float4*)(g_G + kk * FLEN + toff + t4 * 4);
    }
    if (threadIdx.x < HALF) Cs[threadIdx.x] = g_C[toff + threadIdx.x];
    __syncthreads();

    const int b = rowblk * TPB + threadIdx.x;
    if (b >= B) return;

    const float* yrow = enc_l + (size_t)b * HIST + HOFF;   // 16B-aligned
    float* orow = out + (size_t)b * FLEN + toff;            // 16B-aligned

#pragma unroll 1
    for (int pass = 0; pass < HALF / 12; ++pass) {          // 7 passes x 12 t
        const int t0 = pass * 12;
        ull acc[6];
        const ull* cp = (const ull*)(Cs + t0);              // 8B-aligned
#pragma unroll
        for (int i = 0; i < 6; i++) acc[i] = cp[i];

#pragma unroll 1
        for (int kc = 0; kc < 2; ++kc) {                    // k in 2 chunks of 24 (reg cap)
            float y[24];
            const float4* yp = (const float4*)(yrow + kc * 24);
#pragma unroll
            for (int q = 0; q < 6; q++) {
                const float4 v = yp[q];
                y[4 * q + 0] = v.x; y[4 * q + 1] = v.y;
                y[4 * q + 2] = v.z; y[4 * q + 3] = v.w;
            }
#pragma unroll
            for (int k = 0; k < 24; ++k) {
                const ull yv = pack2(y[k], y[k]);           // 1 mov: dup row value
                const ull* gp = (const ull*)(Gs + (kc * 24 + k) * HALF + t0); // 16B-aligned
#pragma unroll
                for (int i = 0; i < 6; i++)
                    acc[i] = ffma2(gp[i], yv, acc[i]);      // 3x LDS.128 feed 6 FFMA2
            }
        }

        float r[12];
#pragma unroll
        for (int i = 0; i < 6; i++) unpack2(acc[i], r[2 * i], r[2 * i + 1]);
        float4* w = (float4*)(orow + t0);
        w[0] = make_float4(r[0], r[1], r[2],  r[3]);
        w[1] = make_float4(r[4], r[5], r[6],  r[7]);
        w[2] = make_float4(r[8], r[9], r[10], r[11]);
    }

    // logvar half: constant broadcast for this t-half
    const float lv = g_lv;
    const float4 lv4 = make_float4(lv, lv, lv, lv);
    float4* q = (float4*)(out + (size_t)B * FLEN + (size_t)b * FLEN + toff);
#pragma unroll
    for (int i = 0; i < HALF / 4; i++) q[i] = lv4;
}

// ---------------------------------------------------------------------------
extern "C" void kernel_launch(void* const* d_in, const int* in_sizes, int n_in,
                              void* d_out, int out_size) {
    const float* enc_l      = (const float*)d_in[0];
    // d_in[1..3] = enc_t, enc_w, enc_s (unused by the reference)
    const float* phi        = (const float*)d_in[4];
    const float* bias       = (const float*)d_in[5];
    const float* log_sigma2 = (const float*)d_in[6];
    const float* mu         = (const float*)d_in[7];
    const float* sigma      = (const float*)d_in[8];

    const int B = in_sizes[0] / HIST;

    precompute_kernel<<<1, 64>>>(phi, bias, log_sigma2, mu, sigma);

    const int nblk = 2 * ((B + TPB - 1) / TPB);   // x2: t-halves
    forecast_kernel<<<nblk, TPB>>>(enc_l, (float*)d_out, B);
}

// round 3
// speedup vs baseline: 1.2462x; 1.2462x over previous
#include <cuda_runtime.h>
#include <cstdint>
#include <math.h>

// Problem constants
#define P     48
#define FLEN  168
#define HALF  84     // t-split: each CTA handles one half of the forecast horizon
#define HIST  336
#define HOFF  288    // HIST - P

// Precomputed affine map: out[b,t] = g_C[t] + sum_k g_G[k*FLEN+t] * enc_l[b*HIST+HOFF+k]
__device__ float g_G[P * FLEN];
__device__ float g_C[FLEN];
__device__ float g_lv;

typedef unsigned long long ull;

__device__ __forceinline__ ull pack2(float a, float b) {
    ull r; asm("mov.b64 %0, {%1, %2};" : "=l"(r) : "f"(a), "f"(b)); return r;
}
__device__ __forceinline__ void unpack2(ull v, float& a, float& b) {
    asm("mov.b64 {%0, %1}, %2;" : "=f"(a), "=f"(b) : "l"(v));
}
// Packed fp32x2 FMA (Blackwell 2x fp32 path; only emitted from PTX fma.rn.f32x2)
__device__ __forceinline__ ull ffma2(ull a, ull b, ull c) {
    ull d; asm("fma.rn.f32x2 %0, %1, %2, %3;" : "=l"(d) : "l"(a), "l"(b), "l"(c)); return d;
}

// ---------------------------------------------------------------------------
// Kernel 1: tiny precompute of the affine map (G, C, logvar const).
// The AR scan is affine in the initial window: track the impulse response
// h[k][i] = d(history[i]) / d(s0[k]) for k<P, and h[P] = the constant term.
// ---------------------------------------------------------------------------
__global__ void precompute_kernel(const float* __restrict__ phi,
                                  const float* __restrict__ bias,
                                  const float* __restrict__ log_sigma2,
                                  const float* __restrict__ mu_p,
                                  const float* __restrict__ sigma_p) {
    __shared__ float h[P + 1][221];   // 221 odd pitch -> conflict-free
    const int k = threadIdx.x;

    float ph[P];
#pragma unroll
    for (int j = 0; j < P; j++) ph[j] = phi[j];

    if (k <= P) {
#pragma unroll
        for (int i = 0; i < P; i++) h[k][i] = (k == i) ? 1.0f : 0.0f;  // k==P row: zeros
        const float b0 = (k == P) ? bias[0] : 0.0f;
        for (int t = 0; t < FLEN; t++) {
            float s0 = 0.f, s1 = 0.f, s2 = 0.f, s3 = 0.f;
#pragma unroll
            for (int j = 0; j < P; j += 4) {
                s0 += ph[j + 0] * h[k][t + j + 0];
                s1 += ph[j + 1] * h[k][t + j + 1];
                s2 += ph[j + 2] * h[k][t + j + 2];
                s3 += ph[j + 3] * h[k][t + j + 3];
            }
            h[k][P + t] = b0 + ((s0 + s1) + (s2 + s3));
        }
    }
    __syncthreads();

    const float mu = *mu_p;
    const float sg = *sigma_p;

    // Fold standardization + un-standardization into C:
    // out = mu + sg*c_t + sum_k W[t,k]*(y_raw - mu)
    for (int t = threadIdx.x; t < FLEN; t += blockDim.x) {
        float sum = 0.0f;
        for (int kk = 0; kk < P; kk++) sum += h[kk][P + t];
        g_C[t] = mu + sg * h[P][P + t] - mu * sum;
    }
    for (int idx = threadIdx.x; idx < P * FLEN; idx += blockDim.x) {
        const int kk = idx / FLEN;
        const int t  = idx - kk * FLEN;
        g_G[idx] = h[kk][P + t];
    }
    if (threadIdx.x == 0) g_lv = log_sigma2[0] + 2.0f * logf(sg);
}

// ---------------------------------------------------------------------------
// Kernel 2: apply. 1 row per thread; f32x2 lanes = (t, t+1) so G comes out of
// shared already packed (broadcast LDS.128, conflict-free). CTA handles one
// t-half (84 cols). y window loaded ONCE into registers (the round-2 mistake
// was reloading it from gmem every pass -> L1 wavefront saturation).
// ---------------------------------------------------------------------------
#define TPB 128

__global__ void __launch_bounds__(TPB, 6)
forecast_kernel(const float* __restrict__ enc_l, float* __restrict__ out, int B) {
    __shared__ float Gs[P * HALF];   // Gs[k*HALF + tt], tt local to this half
    __shared__ float Cs[HALF];

    const int half   = blockIdx.x & 1;
    const int rowblk = blockIdx.x >> 1;
    const int toff   = half * HALF;

    // Stage this half's G slice + C slice into shared
    for (int i = threadIdx.x; i < (P * HALF) / 4; i += TPB) {
        const int kk = i / (HALF / 4);
        const int t4 = i - kk * (HALF / 4);
        ((float4*)Gs)[i] = *(const float4*)(g_G + kk * FLEN + toff + t4 * 4);
    }
    if (threadIdx.x < HALF) Cs[threadIdx.x] = g_C[toff + threadIdx.x];
    __syncthreads();

    const int b = rowblk * TPB + threadIdx.x;
    if (b >= B) return;

    // Load the 48-float window ONCE into registers (12 LDG.128).
    const float4* yp = reinterpret_cast<const float4*>(enc_l + (size_t)b * HIST + HOFF);
    float y[P];
#pragma unroll
    for (int q = 0; q < P / 4; q++) {
        const float4 v = yp[q];
        y[4 * q + 0] = v.x; y[4 * q + 1] = v.y;
        y[4 * q + 2] = v.z; y[4 * q + 3] = v.w;
    }

    float* orow = out + (size_t)b * FLEN + toff;   // 16B-aligned

#pragma unroll 1
    for (int pass = 0; pass < HALF / 12; ++pass) {  // 7 passes x 12 t
        const int t0 = pass * 12;
        ull acc[6];
        const ull* cp = (const ull*)(Cs + t0);
#pragma unroll
        for (int i = 0; i < 6; i++) acc[i] = cp[i];

#pragma unroll
        for (int k = 0; k < P; ++k) {
            const ull yv = pack2(y[k], y[k]);       // 1 mov: dup row value to both lanes
            const ull* gp = (const ull*)(Gs + k * HALF + t0);  // 16B-aligned, broadcast
#pragma unroll
            for (int i = 0; i < 6; i++)
                acc[i] = ffma2(gp[i], yv, acc[i]);  // 3x LDS.128 feed 6 FFMA2
        }

        float r[12];
#pragma unroll
        for (int i = 0; i < 6; i++) unpack2(acc[i], r[2 * i], r[2 * i + 1]);
        float4* w = (float4*)(orow + t0);
        w[0] = make_float4(r[0], r[1], r[2],  r[3]);
        w[1] = make_float4(r[4], r[5], r[6],  r[7]);
        w[2] = make_float4(r[8], r[9], r[10], r[11]);
    }

    // logvar half: constant broadcast for this t-half
    const float lv = g_lv;
    const float4 lv4 = make_float4(lv, lv, lv, lv);
    float4* q = (float4*)(out + (size_t)B * FLEN + (size_t)b * FLEN + toff);
#pragma unroll
    for (int i = 0; i < HALF / 4; i++) q[i] = lv4;
}

// ---------------------------------------------------------------------------
extern "C" void kernel_launch(void* const* d_in, const int* in_sizes, int n_in,
                              void* d_out, int out_size) {
    const float* enc_l      = (const float*)d_in[0];
    // d_in[1..3] = enc_t, enc_w, enc_s (unused by the reference)
    const float* phi        = (const float*)d_in[4];
    const float* bias       = (const float*)d_in[5];
    const float* log_sigma2 = (const float*)d_in[6];
    const float* mu         = (const float*)d_in[7];
    const float* sigma      = (const float*)d_in[8];

    const int B = in_sizes[0] / HIST;

    precompute_kernel<<<1, 64>>>(phi, bias, log_sigma2, mu, sigma);

    const int nblk = 2 * ((B + TPB - 1) / TPB);   // x2: t-halves
    forecast_kernel<<<nblk, TPB>>>(enc_l, (float*)d_out, B);
}